// round 15
// baseline (speedup 1.0000x reference)
#include <cuda_runtime.h>
#include <math.h>

#define NN 100000
#define EE 1600000
#define DD 64
#define TAU 0.5f
#define ITERS 10

#define CB 296
#define LEAFN 8
#define CSRT 512
#define PWT 384
#define NP1 (NN + 1)
#define NCHUNK ((NP1 + CSRT - 1) / CSRT)   // 196
#define RPB ((NN + CB - 1) / CB)           // 338
#define ECAP 7936                          // smem edge cache (62KB)
#define LB   ((NN * 16) / 512)             // 3125 layer tile blocks

// ---------------- scratch ----------------
__device__ float g_X[NN * DD];
__device__ float g_X2[NN * DD];
__device__ float g_ya[NN];
__device__ float g_yb[NN];
__device__ float g_norms[ITERS];
__device__ float g_nleaf[ITERS * LEAFN * 32];
__device__ int   g_rsA[NP1];
__device__ int   g_rsL[NP1];
__device__ int   g_rankA[EE];
__device__ int   g_rankL[EE];
__device__ int2  g_eA[EE];
__device__ int2  g_eL[EE];
__device__ int   g_bsumA[NCHUNK];
__device__ int   g_bsumL[NCHUNK];
__device__ unsigned g_leaf[LEAFN * 32];
__device__ unsigned g_root;
__device__ volatile unsigned g_sense;

// ---------------------------------------------------------------------------
__device__ __forceinline__ void grid_sync_tree(unsigned* sense_s, int gb,
                                               int gsz, int it_norm) {
    __syncthreads();
    if (threadIdx.x == 0) {
        unsigned s = *sense_s + 1;
        *sense_s = s;
        __threadfence();
        int leaf = gb & (LEAFN - 1);
        unsigned p = atomicAdd(&g_leaf[leaf * 32], 1u);
        if (p == (unsigned)(gsz / LEAFN) - 1) {
            g_leaf[leaf * 32] = 0;
            __threadfence();
            unsigned q = atomicAdd(&g_root, 1u);
            if (q == LEAFN - 1) {
                g_root = 0;
                if (it_norm >= 0) {
                    float t = 0.f;
#pragma unroll
                    for (int l = 0; l < LEAFN; l++)
                        t += __ldcg(&g_nleaf[(it_norm * LEAFN + l) * 32]);
                    __stcg(&g_norms[it_norm], t);
                }
                __threadfence();
                g_sense = s;
            } else {
                while (g_sense != s) __nanosleep(32);
            }
        } else {
            while (g_sense != s) __nanosleep(32);
        }
    }
    __syncthreads();
}

// ---------------------------------------------------------------------------
// CSR build: rank-trick hist (A+L), scans (A+L), atomic-free scatter A.
__global__ __launch_bounds__(CSRT, 2)
void csr_build_kernel(const int* __restrict__ Arow, const int* __restrict__ Acol,
                      const float* __restrict__ Aval,
                      const int* __restrict__ Lrow, int E) {
    __shared__ unsigned sense;
    __shared__ int sm[CSRT];
    const int tid = threadIdx.x;
    const int gtid = blockIdx.x * CSRT + tid;
    const int gs = gridDim.x * CSRT;
    if (tid == 0) sense = g_sense;

    for (int i = gtid; i < NP1; i += gs) { __stcg(&g_rsA[i], 0); __stcg(&g_rsL[i], 0); }
    for (int i = gtid; i < ITERS * LEAFN * 32; i += gs) __stcg(&g_nleaf[i], 0.f);
    if (gtid < ITERS) __stcg(&g_norms[gtid], 0.f);
    grid_sync_tree(&sense, blockIdx.x, CB, -1);

    {   // histogram A + L with rank capture, 2x unrolled
        int e = gtid;
        for (; e + gs < E; e += 2 * gs) {
            int a0 = __ldg(Arow + e), a1 = __ldg(Arow + e + gs);
            int l0 = __ldg(Lrow + e), l1 = __ldg(Lrow + e + gs);
            int ra0 = atomicAdd(&g_rsA[a0 + 1], 1);
            int ra1 = atomicAdd(&g_rsA[a1 + 1], 1);
            int rl0 = atomicAdd(&g_rsL[l0 + 1], 1);
            int rl1 = atomicAdd(&g_rsL[l1 + 1], 1);
            __stcg(&g_rankA[e], ra0);      __stcg(&g_rankA[e + gs], ra1);
            __stcg(&g_rankL[e], rl0);      __stcg(&g_rankL[e + gs], rl1);
        }
        if (e < E) {
            __stcg(&g_rankA[e], atomicAdd(&g_rsA[__ldg(Arow + e) + 1], 1));
            __stcg(&g_rankL[e], atomicAdd(&g_rsL[__ldg(Lrow + e) + 1], 1));
        }
    }
    grid_sync_tree(&sense, blockIdx.x, CB, -1);

    // per-chunk inclusive scan for BOTH arrays
    for (int chunk = blockIdx.x; chunk < 2 * NCHUNK; chunk += gridDim.x) {
        int* arr = (chunk < NCHUNK) ? g_rsA : g_rsL;
        int* bs  = (chunk < NCHUNK) ? g_bsumA : g_bsumL;
        int cc = (chunk < NCHUNK) ? chunk : chunk - NCHUNK;
        int idx = cc * CSRT + tid;
        int x = (idx < NP1) ? __ldcg(&arr[idx]) : 0;
        sm[tid] = x;
        __syncthreads();
#pragma unroll
        for (int off = 1; off < CSRT; off <<= 1) {
            int t = (tid >= off) ? sm[tid - off] : 0;
            __syncthreads();
            sm[tid] += t;
            __syncthreads();
        }
        if (idx < NP1) __stcg(&arr[idx], sm[tid]);
        if (tid == CSRT - 1) __stcg(&bs[cc], sm[tid]);
        __syncthreads();
    }
    grid_sync_tree(&sense, blockIdx.x, CB, -1);

    if (blockIdx.x < 2) {
        int* bs = blockIdx.x ? g_bsumL : g_bsumA;
        int x = (tid < NCHUNK) ? __ldcg(&bs[tid]) : 0;
        sm[tid] = x;
        __syncthreads();
#pragma unroll
        for (int off = 1; off < CSRT; off <<= 1) {
            int t = (tid >= off) ? sm[tid - off] : 0;
            __syncthreads();
            sm[tid] += t;
            __syncthreads();
        }
        if (tid < NCHUNK) __stcg(&bs[tid], sm[tid]);
    }
    grid_sync_tree(&sense, blockIdx.x, CB, -1);

    for (int i = gtid; i < NP1; i += gs) {
        int chunk = i / CSRT;
        int a = __ldcg(&g_rsA[i]) + (chunk ? __ldcg(&g_bsumA[chunk - 1]) : 0);
        int l = __ldcg(&g_rsL[i]) + (chunk ? __ldcg(&g_bsumL[chunk - 1]) : 0);
        __stcg(&g_rsA[i], a);
        __stcg(&g_rsL[i], l);
    }
    grid_sync_tree(&sense, blockIdx.x, CB, -1);

    {   // scatter A: atomic-free (pos = rsA[row] + rank), 2x unrolled
        int e = gtid;
        for (; e + gs < E; e += 2 * gs) {
            int ra0 = __ldg(Arow + e), ra1 = __ldg(Arow + e + gs);
            int ca0 = __ldg(Acol + e), ca1 = __ldg(Acol + e + gs);
            float va0 = __ldg(Aval + e), va1 = __ldg(Aval + e + gs);
            int k0 = __ldcg(&g_rankA[e]), k1 = __ldcg(&g_rankA[e + gs]);
            int p0 = __ldg(&g_rsA[ra0]) + k0;
            int p1 = __ldg(&g_rsA[ra1]) + k1;
            g_eA[p0] = make_int2(ca0, __float_as_int(va0));
            g_eA[p1] = make_int2(ca1, __float_as_int(va1));
        }
        if (e < E) {
            int ra = __ldg(Arow + e);
            int pos = __ldg(&g_rsA[ra]) + __ldcg(&g_rankA[e]);
            g_eA[pos] = make_int2(__ldg(Acol + e), __float_as_int(__ldg(Aval + e)));
        }
    }
}

// ---------------------------------------------------------------------------
// Layer: fused SpMM + Linear tiles + distributed atomic-free L scatter.
// (512,2): 64-reg budget for an MLP8 gather (8 row-gathers in flight).
__global__ __launch_bounds__(512, 2)
void layer_kernel(const float* __restrict__ Xin, float* __restrict__ Xout,
                  const float* __restrict__ W, const float* __restrict__ Ws,
                  float* __restrict__ vout, int layer2,
                  const int* __restrict__ Lrow, const int* __restrict__ Lcol,
                  const float* __restrict__ Lval, int ebase, int eend) {
    __shared__ float  Wt[DD * DD];
    __shared__ float4 AX4[32 * 17];
    __shared__ float4 WsS[16];
    const int tid = threadIdx.x;

    for (int i = tid; i < DD * DD; i += 512) {
        int k = i >> 6, d = i & 63;
        Wt[k * DD + d] = __ldg(&W[d * DD + k]);
    }
    if (tid < 16) WsS[tid] = __ldg(&((const float4*)Ws)[tid]);
    __syncthreads();

    const int gt = blockIdx.x * 512 + tid;
    const int r = gt >> 4;
    const int c = tid & 15;
    const int slot = tid >> 4;

    {
        int s = __ldg(&g_rsA[r]);
        int e = __ldg(&g_rsA[r + 1]);
        float4 acc = make_float4(0.f, 0.f, 0.f, 0.f);
        int i = s;
        if (i < e && (i & 1)) {
            int2 p = __ldg(&g_eA[i]);
            float v = __int_as_float(p.y);
            float4 a = __ldg(((const float4*)(Xin + (size_t)p.x * DD)) + c);
            acc.x += v * a.x; acc.y += v * a.y; acc.z += v * a.z; acc.w += v * a.w;
            i++;
        }
        for (; i + 7 < e; i += 8) {      // MLP8: 8 row gathers in flight
            int4 q0 = __ldcs((const int4*)(g_eA + i));
            int4 q1 = __ldcs((const int4*)(g_eA + i + 2));
            int4 q2 = __ldcs((const int4*)(g_eA + i + 4));
            int4 q3 = __ldcs((const int4*)(g_eA + i + 6));
            float4 x0 = __ldg(((const float4*)(Xin + (size_t)q0.x * DD)) + c);
            float4 x1 = __ldg(((const float4*)(Xin + (size_t)q0.z * DD)) + c);
            float4 x2 = __ldg(((const float4*)(Xin + (size_t)q1.x * DD)) + c);
            float4 x3 = __ldg(((const float4*)(Xin + (size_t)q1.z * DD)) + c);
            float4 x4 = __ldg(((const float4*)(Xin + (size_t)q2.x * DD)) + c);
            float4 x5 = __ldg(((const float4*)(Xin + (size_t)q2.z * DD)) + c);
            float4 x6 = __ldg(((const float4*)(Xin + (size_t)q3.x * DD)) + c);
            float4 x7 = __ldg(((const float4*)(Xin + (size_t)q3.z * DD)) + c);
            float v0 = __int_as_float(q0.y), v1 = __int_as_float(q0.w);
            float v2 = __int_as_float(q1.y), v3 = __int_as_float(q1.w);
            float v4 = __int_as_float(q2.y), v5 = __int_as_float(q2.w);
            float v6 = __int_as_float(q3.y), v7 = __int_as_float(q3.w);
            acc.x += v0*x0.x + v1*x1.x + v2*x2.x + v3*x3.x;
            acc.y += v0*x0.y + v1*x1.y + v2*x2.y + v3*x3.y;
            acc.z += v0*x0.z + v1*x1.z + v2*x2.z + v3*x3.z;
            acc.w += v0*x0.w + v1*x1.w + v2*x2.w + v3*x3.w;
            acc.x += v4*x4.x + v5*x5.x + v6*x6.x + v7*x7.x;
            acc.y += v4*x4.y + v5*x5.y + v6*x6.y + v7*x7.y;
            acc.z += v4*x4.z + v5*x5.z + v6*x6.z + v7*x7.z;
            acc.w += v4*x4.w + v5*x5.w + v6*x6.w + v7*x7.w;
        }
        for (; i + 3 < e; i += 4) {      // MLP4 tail
            int4 q0 = __ldcs((const int4*)(g_eA + i));
            int4 q1 = __ldcs((const int4*)(g_eA + i + 2));
            float4 x0 = __ldg(((const float4*)(Xin + (size_t)q0.x * DD)) + c);
            float4 x1 = __ldg(((const float4*)(Xin + (size_t)q0.z * DD)) + c);
            float4 x2 = __ldg(((const float4*)(Xin + (size_t)q1.x * DD)) + c);
            float4 x3 = __ldg(((const float4*)(Xin + (size_t)q1.z * DD)) + c);
            float v0 = __int_as_float(q0.y), v1 = __int_as_float(q0.w);
            float v2 = __int_as_float(q1.y), v3 = __int_as_float(q1.w);
            acc.x += v0*x0.x + v1*x1.x + v2*x2.x + v3*x3.x;
            acc.y += v0*x0.y + v1*x1.y + v2*x2.y + v3*x3.y;
            acc.z += v0*x0.z + v1*x1.z + v2*x2.z + v3*x3.z;
            acc.w += v0*x0.w + v1*x1.w + v2*x2.w + v3*x3.w;
        }
        for (; i < e; i++) {
            int2 p = __ldg(&g_eA[i]);
            float v = __int_as_float(p.y);
            float4 a = __ldg(((const float4*)(Xin + (size_t)p.x * DD)) + c);
            acc.x += v * a.x; acc.y += v * a.y; acc.z += v * a.z; acc.w += v * a.w;
        }
        AX4[slot * 17 + c] = acc;
    }
    __syncthreads();

    if (tid < 256) {
        const int q = tid >> 4;
        const int rb = q * 2;
        float4 o0 = make_float4(0.f,0.f,0.f,0.f), o1 = o0;
#pragma unroll
        for (int k4 = 0; k4 < 16; k4++) {
            float4 a0 = AX4[(rb + 0) * 17 + k4];
            float4 a1 = AX4[(rb + 1) * 17 + k4];
            float4 w0 = ((const float4*)(Wt + (k4 * 4 + 0) * DD))[c];
            o0.x += a0.x*w0.x; o0.y += a0.x*w0.y; o0.z += a0.x*w0.z; o0.w += a0.x*w0.w;
            o1.x += a1.x*w0.x; o1.y += a1.x*w0.y; o1.z += a1.x*w0.z; o1.w += a1.x*w0.w;
            float4 w1 = ((const float4*)(Wt + (k4 * 4 + 1) * DD))[c];
            o0.x += a0.y*w1.x; o0.y += a0.y*w1.y; o0.z += a0.y*w1.z; o0.w += a0.y*w1.w;
            o1.x += a1.y*w1.x; o1.y += a1.y*w1.y; o1.z += a1.y*w1.z; o1.w += a1.y*w1.w;
            float4 w2 = ((const float4*)(Wt + (k4 * 4 + 2) * DD))[c];
            o0.x += a0.z*w2.x; o0.y += a0.z*w2.y; o0.z += a0.z*w2.z; o0.w += a0.z*w2.w;
            o1.x += a1.z*w2.x; o1.y += a1.z*w2.y; o1.z += a1.z*w2.z; o1.w += a1.z*w2.w;
            float4 w3 = ((const float4*)(Wt + (k4 * 4 + 3) * DD))[c];
            o0.x += a0.w*w3.x; o0.y += a0.w*w3.y; o0.z += a0.w*w3.z; o0.w += a0.w*w3.w;
            o1.x += a1.w*w3.x; o1.y += a1.w*w3.y; o1.z += a1.w*w3.z; o1.w += a1.w*w3.w;
        }

        const int rg0 = blockIdx.x * 32 + rb;
        float4 oo[2] = {o0, o1};
#pragma unroll
        for (int i2 = 0; i2 < 2; i2++) {
            int rg = rg0 + i2;
            float4 xi = __ldg(((const float4*)(Xin + (size_t)rg * DD)) + c);
            float4 res;
            res.x = xi.x + fmaxf(oo[i2].x, 0.f);
            res.y = xi.y + fmaxf(oo[i2].y, 0.f);
            res.z = xi.z + fmaxf(oo[i2].z, 0.f);
            res.w = xi.w + fmaxf(oo[i2].w, 0.f);
            ((float4*)(Xout + (size_t)rg * DD))[c] = res;
            if (layer2) {
                float4 ws = WsS[c];
                float pv = res.x*ws.x + res.y*ws.y + res.z*ws.z + res.w*ws.w;
                pv += __shfl_xor_sync(0xFFFFFFFFu, pv, 8, 16);
                pv += __shfl_xor_sync(0xFFFFFFFFu, pv, 4, 16);
                pv += __shfl_xor_sync(0xFFFFFFFFu, pv, 2, 16);
                pv += __shfl_xor_sync(0xFFFFFFFFu, pv, 1, 16);
                if (c == 0) vout[rg] = pv;
            }
        }
    }

    // ---- distributed L scatter (atomic-free) ----
    {
        const int gstride = LB * 512;
        for (int e = ebase + blockIdx.x * 512 + tid; e < eend; e += gstride) {
            int row = __ldg(Lrow + e);
            int pos = __ldg(&g_rsL[row]) + __ldcg(&g_rankL[e]);
            g_eL[pos] = make_int2(__ldg(Lcol + e),
                                  __float_as_int(__ldg(Lval + e)));
        }
    }
}

// ---------------------------------------------------------------------------
// Power (best-known body): 1 thread/row, smem edge cache, __ldcg gathers,
// MLP8, lazy norm (1 barrier/iter), tree barrier with norm fold.
__global__ __launch_bounds__(PWT, 2)
void power_kernel(float* __restrict__ out) {
    extern __shared__ int2 sE[];
    __shared__ unsigned sense;
    __shared__ float wsum[PWT / 32];
    const int tid = threadIdx.x;
    const int lane = tid & 31, wid = tid >> 5;
    if (tid == 0) sense = g_sense;

    const int r0 = blockIdx.x * RPB;
    const int r1 = (r0 + RPB < NN) ? r0 + RPB : NN;
    const int s0 = __ldg(&g_rsL[r0]);
    const int e0 = __ldg(&g_rsL[r1]);
    const int cnt = min(e0 - s0, ECAP);
    for (int i = tid; i < cnt; i += PWT) sE[i] = __ldg(&g_eL[s0 + i]);

    const int r = r0 + tid;
    const bool active = (tid < RPB) && (r < NN);
    int s = 0, e = 0;
    if (active) {
        s = __ldg(&g_rsL[r]) - s0;
        e = __ldg(&g_rsL[r + 1]) - s0;
    }
    __syncthreads();

    float y = 0.f;
    for (int it = 0; it < ITERS; it++) {
        float alpha = 1.f;
        if (it > 0)
            alpha = 1.f / fmaxf(sqrtf(__ldcg(&g_norms[it - 1])), 1e-12f);
        const float* src = (it & 1) ? g_yb : g_ya;
        float* dst = (it & 1) ? g_ya : g_yb;

        float acc = 0.f;
        if (active) {
            int i = s;
            int elim = (e < ECAP) ? e : ECAP;
            for (; i + 7 < elim; i += 8) {
                int2 p0 = sE[i],     p1 = sE[i + 1], p2 = sE[i + 2], p3 = sE[i + 3];
                int2 p4 = sE[i + 4], p5 = sE[i + 5], p6 = sE[i + 6], p7 = sE[i + 7];
                float v0 = __ldcg(&src[p0.x]);
                float v1 = __ldcg(&src[p1.x]);
                float v2 = __ldcg(&src[p2.x]);
                float v3 = __ldcg(&src[p3.x]);
                float v4 = __ldcg(&src[p4.x]);
                float v5 = __ldcg(&src[p5.x]);
                float v6 = __ldcg(&src[p6.x]);
                float v7 = __ldcg(&src[p7.x]);
                acc += __int_as_float(p0.y) * v0 + __int_as_float(p1.y) * v1;
                acc += __int_as_float(p2.y) * v2 + __int_as_float(p3.y) * v3;
                acc += __int_as_float(p4.y) * v4 + __int_as_float(p5.y) * v5;
                acc += __int_as_float(p6.y) * v6 + __int_as_float(p7.y) * v7;
            }
            for (; i < elim; i++) {
                int2 p = sE[i];
                acc += __int_as_float(p.y) * __ldcg(&src[p.x]);
            }
            for (; i < e; i++) {
                int2 p = __ldg(&g_eL[s0 + i]);
                acc += __int_as_float(p.y) * __ldcg(&src[p.x]);
            }
        }

        float sq = 0.f;
        if (active) {
            float z = alpha * acc;
            float sg = (z > 0.f) ? 1.f : ((z < 0.f) ? -1.f : 0.f);
            y = z - TAU * sg;
            sq = y * y;
            __stcg(&dst[r], y);
        }
#pragma unroll
        for (int off = 16; off > 0; off >>= 1)
            sq += __shfl_down_sync(0xFFFFFFFFu, sq, off);
        if (lane == 0) wsum[wid] = sq;
        __syncthreads();
        if (wid == 0) {
            sq = (lane < (PWT >> 5)) ? wsum[lane] : 0.f;
#pragma unroll
            for (int off = 16; off > 0; off >>= 1)
                sq += __shfl_down_sync(0xFFFFFFFFu, sq, off);
            if (lane == 0)
                atomicAdd(&g_nleaf[(it * LEAFN + (blockIdx.x & (LEAFN - 1))) * 32], sq);
        }
        grid_sync_tree(&sense, blockIdx.x, CB, it);
    }

    if (active) {
        float inv = 1.f / fmaxf(sqrtf(__ldcg(&g_norms[ITERS - 1])), 1e-12f);
        out[r] = y * inv;
    }
}

// ---------------------------------------------------------------------------
extern "C" void kernel_launch(void* const* d_in, const int* in_sizes, int n_in,
                              void* d_out, int out_size) {
    const int*   A_row = (const int*)d_in[0];
    const int*   A_col = (const int*)d_in[1];
    const float* A_val = (const float*)d_in[2];
    const int*   L_row = (const int*)d_in[3];
    const int*   L_col = (const int*)d_in[4];
    const float* L_val = (const float*)d_in[5];
    const float* embed = (const float*)d_in[6];
    const float* W1    = (const float*)d_in[7];
    const float* W2    = (const float*)d_in[8];
    const float* Ws    = (const float*)d_in[9];
    const int E = in_sizes[0];
    float* out = (float*)d_out;

    float *X, *X2, *ya;
    cudaGetSymbolAddress((void**)&X,  g_X);
    cudaGetSymbolAddress((void**)&X2, g_X2);
    cudaGetSymbolAddress((void**)&ya, g_ya);

    static int smem_set = 0;
    if (!smem_set) {
        cudaFuncSetAttribute(power_kernel,
                             cudaFuncAttributeMaxDynamicSharedMemorySize,
                             ECAP * (int)sizeof(int2));
        smem_set = 1;
    }

    // 1) CSR: ranks A+L, scans A+L, atomic-free scatter A
    csr_build_kernel<<<CB, CSRT>>>(A_row, A_col, A_val, L_row, E);

    // 2-3) layers; each also scatters half the L edges (atomic-free)
    const int Ehalf = E / 2;
    layer_kernel<<<LB, 512>>>(embed, X,  W1, Ws, ya, 0,
                              L_row, L_col, L_val, 0, Ehalf);
    layer_kernel<<<LB, 512>>>(X,     X2, W2, Ws, ya, 1,
                              L_row, L_col, L_val, Ehalf, E);

    // 4) power iterations
    power_kernel<<<CB, PWT, ECAP * sizeof(int2)>>>(out);
}

// round 16
// speedup vs baseline: 1.0531x; 1.0531x over previous
#include <cuda_runtime.h>
#include <math.h>

#define NN 100000
#define EE 1600000
#define DD 64
#define TAU 0.5f
#define ITERS 10

#define CB 296
#define LEAFN 8
#define CSRT 512
#define PWT 384
#define NP1 (NN + 1)
#define NCHUNK ((NP1 + CSRT - 1) / CSRT)   // 196
#define RPB ((NN + CB - 1) / CB)           // 338
#define ECAP 7936                          // smem edge cache (62KB)
#define LB   ((NN * 16) / 512)             // 3125 layer tile blocks

// ---------------- scratch ----------------
__device__ float g_X[NN * DD];
__device__ float g_ya[NN];
__device__ float g_yb[NN];
__device__ float g_norms[ITERS];
__device__ float g_nleaf[ITERS * LEAFN * 32];
__device__ int   g_rsA[NP1];
__device__ int   g_rsL[NP1];
__device__ int   g_rankA[EE];
__device__ int   g_rankL[EE];
__device__ int2  g_eA[EE];
__device__ int2  g_eL[EE];
__device__ int   g_bsumA[NCHUNK];
__device__ int   g_bsumL[NCHUNK];
__device__ unsigned g_leaf[LEAFN * 32];
__device__ unsigned g_root;
__device__ volatile unsigned g_sense;

// ---------------------------------------------------------------------------
__device__ __forceinline__ void grid_sync_tree(unsigned* sense_s, int gb,
                                               int gsz, int it_norm) {
    __syncthreads();
    if (threadIdx.x == 0) {
        unsigned s = *sense_s + 1;
        *sense_s = s;
        __threadfence();
        int leaf = gb & (LEAFN - 1);
        unsigned p = atomicAdd(&g_leaf[leaf * 32], 1u);
        if (p == (unsigned)(gsz / LEAFN) - 1) {
            g_leaf[leaf * 32] = 0;
            __threadfence();
            unsigned q = atomicAdd(&g_root, 1u);
            if (q == LEAFN - 1) {
                g_root = 0;
                if (it_norm >= 0) {
                    float t = 0.f;
#pragma unroll
                    for (int l = 0; l < LEAFN; l++)
                        t += __ldcg(&g_nleaf[(it_norm * LEAFN + l) * 32]);
                    __stcg(&g_norms[it_norm], t);
                }
                __threadfence();
                g_sense = s;
            } else {
                while (g_sense != s) __nanosleep(32);
            }
        } else {
            while (g_sense != s) __nanosleep(32);
        }
    }
    __syncthreads();
}

// ---------------------------------------------------------------------------
// CSR build: rank-trick hist (A+L), scans (A+L), atomic-free scatter A.
__global__ __launch_bounds__(CSRT, 2)
void csr_build_kernel(const int* __restrict__ Arow, const int* __restrict__ Acol,
                      const float* __restrict__ Aval,
                      const int* __restrict__ Lrow, int E) {
    __shared__ unsigned sense;
    __shared__ int sm[CSRT];
    const int tid = threadIdx.x;
    const int gtid = blockIdx.x * CSRT + tid;
    const int gs = gridDim.x * CSRT;
    if (tid == 0) sense = g_sense;

    for (int i = gtid; i < NP1; i += gs) { __stcg(&g_rsA[i], 0); __stcg(&g_rsL[i], 0); }
    for (int i = gtid; i < ITERS * LEAFN * 32; i += gs) __stcg(&g_nleaf[i], 0.f);
    if (gtid < ITERS) __stcg(&g_norms[gtid], 0.f);
    grid_sync_tree(&sense, blockIdx.x, CB, -1);

    {   // histogram A + L with rank capture, 2x unrolled
        int e = gtid;
        for (; e + gs < E; e += 2 * gs) {
            int a0 = __ldg(Arow + e), a1 = __ldg(Arow + e + gs);
            int l0 = __ldg(Lrow + e), l1 = __ldg(Lrow + e + gs);
            int ra0 = atomicAdd(&g_rsA[a0 + 1], 1);
            int ra1 = atomicAdd(&g_rsA[a1 + 1], 1);
            int rl0 = atomicAdd(&g_rsL[l0 + 1], 1);
            int rl1 = atomicAdd(&g_rsL[l1 + 1], 1);
            __stcg(&g_rankA[e], ra0);      __stcg(&g_rankA[e + gs], ra1);
            __stcg(&g_rankL[e], rl0);      __stcg(&g_rankL[e + gs], rl1);
        }
        if (e < E) {
            __stcg(&g_rankA[e], atomicAdd(&g_rsA[__ldg(Arow + e) + 1], 1));
            __stcg(&g_rankL[e], atomicAdd(&g_rsL[__ldg(Lrow + e) + 1], 1));
        }
    }
    grid_sync_tree(&sense, blockIdx.x, CB, -1);

    // per-chunk inclusive scan for BOTH arrays
    for (int chunk = blockIdx.x; chunk < 2 * NCHUNK; chunk += gridDim.x) {
        int* arr = (chunk < NCHUNK) ? g_rsA : g_rsL;
        int* bs  = (chunk < NCHUNK) ? g_bsumA : g_bsumL;
        int cc = (chunk < NCHUNK) ? chunk : chunk - NCHUNK;
        int idx = cc * CSRT + tid;
        int x = (idx < NP1) ? __ldcg(&arr[idx]) : 0;
        sm[tid] = x;
        __syncthreads();
#pragma unroll
        for (int off = 1; off < CSRT; off <<= 1) {
            int t = (tid >= off) ? sm[tid - off] : 0;
            __syncthreads();
            sm[tid] += t;
            __syncthreads();
        }
        if (idx < NP1) __stcg(&arr[idx], sm[tid]);
        if (tid == CSRT - 1) __stcg(&bs[cc], sm[tid]);
        __syncthreads();
    }
    grid_sync_tree(&sense, blockIdx.x, CB, -1);

    if (blockIdx.x < 2) {
        int* bs = blockIdx.x ? g_bsumL : g_bsumA;
        int x = (tid < NCHUNK) ? __ldcg(&bs[tid]) : 0;
        sm[tid] = x;
        __syncthreads();
#pragma unroll
        for (int off = 1; off < CSRT; off <<= 1) {
            int t = (tid >= off) ? sm[tid - off] : 0;
            __syncthreads();
            sm[tid] += t;
            __syncthreads();
        }
        if (tid < NCHUNK) __stcg(&bs[tid], sm[tid]);
    }
    grid_sync_tree(&sense, blockIdx.x, CB, -1);

    for (int i = gtid; i < NP1; i += gs) {
        int chunk = i / CSRT;
        int a = __ldcg(&g_rsA[i]) + (chunk ? __ldcg(&g_bsumA[chunk - 1]) : 0);
        int l = __ldcg(&g_rsL[i]) + (chunk ? __ldcg(&g_bsumL[chunk - 1]) : 0);
        __stcg(&g_rsA[i], a);
        __stcg(&g_rsL[i], l);
    }
    grid_sync_tree(&sense, blockIdx.x, CB, -1);

    {   // scatter A: atomic-free (pos = rsA[row] + rank), 2x unrolled
        int e = gtid;
        for (; e + gs < E; e += 2 * gs) {
            int ra0 = __ldg(Arow + e), ra1 = __ldg(Arow + e + gs);
            int ca0 = __ldg(Acol + e), ca1 = __ldg(Acol + e + gs);
            float va0 = __ldg(Aval + e), va1 = __ldg(Aval + e + gs);
            int k0 = __ldcg(&g_rankA[e]), k1 = __ldcg(&g_rankA[e + gs]);
            int p0 = __ldg(&g_rsA[ra0]) + k0;
            int p1 = __ldg(&g_rsA[ra1]) + k1;
            g_eA[p0] = make_int2(ca0, __float_as_int(va0));
            g_eA[p1] = make_int2(ca1, __float_as_int(va1));
        }
        if (e < E) {
            int ra = __ldg(Arow + e);
            int pos = __ldg(&g_rsA[ra]) + __ldcg(&g_rankA[e]);
            g_eA[pos] = make_int2(__ldg(Acol + e), __float_as_int(__ldg(Aval + e)));
        }
    }
}

// ---------------------------------------------------------------------------
// Layer: fused SpMM + Linear tiles + distributed atomic-free L scatter.
// (512,3), MLP4 gather (best-known). layer2 skips the Xout store — only the
// score v[n] is needed downstream.
__global__ __launch_bounds__(512, 3)
void layer_kernel(const float* __restrict__ Xin, float* __restrict__ Xout,
                  const float* __restrict__ W, const float* __restrict__ Ws,
                  float* __restrict__ vout, int layer2,
                  const int* __restrict__ Lrow, const int* __restrict__ Lcol,
                  const float* __restrict__ Lval, int ebase, int eend) {
    __shared__ float  Wt[DD * DD];
    __shared__ float4 AX4[32 * 17];
    __shared__ float4 WsS[16];
    const int tid = threadIdx.x;

    for (int i = tid; i < DD * DD; i += 512) {
        int k = i >> 6, d = i & 63;
        Wt[k * DD + d] = __ldg(&W[d * DD + k]);
    }
    if (tid < 16) WsS[tid] = __ldg(&((const float4*)Ws)[tid]);
    __syncthreads();

    const int gt = blockIdx.x * 512 + tid;
    const int r = gt >> 4;
    const int c = tid & 15;
    const int slot = tid >> 4;

    {
        int s = __ldg(&g_rsA[r]);
        int e = __ldg(&g_rsA[r + 1]);
        float4 acc = make_float4(0.f, 0.f, 0.f, 0.f);
        int i = s;
        if (i < e && (i & 1)) {
            int2 p = __ldg(&g_eA[i]);
            float v = __int_as_float(p.y);
            float4 a = __ldg(((const float4*)(Xin + (size_t)p.x * DD)) + c);
            acc.x += v * a.x; acc.y += v * a.y; acc.z += v * a.z; acc.w += v * a.w;
            i++;
        }
        for (; i + 3 < e; i += 4) {
            int4 q0 = __ldcs((const int4*)(g_eA + i));
            int4 q1 = __ldcs((const int4*)(g_eA + i + 2));
            float4 a  = __ldg(((const float4*)(Xin + (size_t)q0.x * DD)) + c);
            float4 b  = __ldg(((const float4*)(Xin + (size_t)q0.z * DD)) + c);
            float4 d2 = __ldg(((const float4*)(Xin + (size_t)q1.x * DD)) + c);
            float4 f  = __ldg(((const float4*)(Xin + (size_t)q1.z * DD)) + c);
            float v0 = __int_as_float(q0.y), v1 = __int_as_float(q0.w);
            float v2 = __int_as_float(q1.y), v3 = __int_as_float(q1.w);
            acc.x += v0 * a.x + v1 * b.x + v2 * d2.x + v3 * f.x;
            acc.y += v0 * a.y + v1 * b.y + v2 * d2.y + v3 * f.y;
            acc.z += v0 * a.z + v1 * b.z + v2 * d2.z + v3 * f.z;
            acc.w += v0 * a.w + v1 * b.w + v2 * d2.w + v3 * f.w;
        }
        for (; i < e; i++) {
            int2 p = __ldg(&g_eA[i]);
            float v = __int_as_float(p.y);
            float4 a = __ldg(((const float4*)(Xin + (size_t)p.x * DD)) + c);
            acc.x += v * a.x; acc.y += v * a.y; acc.z += v * a.z; acc.w += v * a.w;
        }
        AX4[slot * 17 + c] = acc;
    }
    __syncthreads();

    if (tid < 256) {
        const int q = tid >> 4;
        const int rb = q * 2;
        float4 o0 = make_float4(0.f,0.f,0.f,0.f), o1 = o0;
#pragma unroll
        for (int k4 = 0; k4 < 16; k4++) {
            float4 a0 = AX4[(rb + 0) * 17 + k4];
            float4 a1 = AX4[(rb + 1) * 17 + k4];
            float4 w0 = ((const float4*)(Wt + (k4 * 4 + 0) * DD))[c];
            o0.x += a0.x*w0.x; o0.y += a0.x*w0.y; o0.z += a0.x*w0.z; o0.w += a0.x*w0.w;
            o1.x += a1.x*w0.x; o1.y += a1.x*w0.y; o1.z += a1.x*w0.z; o1.w += a1.x*w0.w;
            float4 w1 = ((const float4*)(Wt + (k4 * 4 + 1) * DD))[c];
            o0.x += a0.y*w1.x; o0.y += a0.y*w1.y; o0.z += a0.y*w1.z; o0.w += a0.y*w1.w;
            o1.x += a1.y*w1.x; o1.y += a1.y*w1.y; o1.z += a1.y*w1.z; o1.w += a1.y*w1.w;
            float4 w2 = ((const float4*)(Wt + (k4 * 4 + 2) * DD))[c];
            o0.x += a0.z*w2.x; o0.y += a0.z*w2.y; o0.z += a0.z*w2.z; o0.w += a0.z*w2.w;
            o1.x += a1.z*w2.x; o1.y += a1.z*w2.y; o1.z += a1.z*w2.z; o1.w += a1.z*w2.w;
            float4 w3 = ((const float4*)(Wt + (k4 * 4 + 3) * DD))[c];
            o0.x += a0.w*w3.x; o0.y += a0.w*w3.y; o0.z += a0.w*w3.z; o0.w += a0.w*w3.w;
            o1.x += a1.w*w3.x; o1.y += a1.w*w3.y; o1.z += a1.w*w3.z; o1.w += a1.w*w3.w;
        }

        const int rg0 = blockIdx.x * 32 + rb;
        float4 oo[2] = {o0, o1};
#pragma unroll
        for (int i2 = 0; i2 < 2; i2++) {
            int rg = rg0 + i2;
            float4 xi = __ldg(((const float4*)(Xin + (size_t)rg * DD)) + c);
            float4 res;
            res.x = xi.x + fmaxf(oo[i2].x, 0.f);
            res.y = xi.y + fmaxf(oo[i2].y, 0.f);
            res.z = xi.z + fmaxf(oo[i2].z, 0.f);
            res.w = xi.w + fmaxf(oo[i2].w, 0.f);
            if (!layer2) {
                ((float4*)(Xout + (size_t)rg * DD))[c] = res;
            } else {
                // features not needed downstream — only the score
                float4 ws = WsS[c];
                float pv = res.x*ws.x + res.y*ws.y + res.z*ws.z + res.w*ws.w;
                pv += __shfl_xor_sync(0xFFFFFFFFu, pv, 8, 16);
                pv += __shfl_xor_sync(0xFFFFFFFFu, pv, 4, 16);
                pv += __shfl_xor_sync(0xFFFFFFFFu, pv, 2, 16);
                pv += __shfl_xor_sync(0xFFFFFFFFu, pv, 1, 16);
                if (c == 0) vout[rg] = pv;
            }
        }
    }

    // ---- distributed L scatter (atomic-free) ----
    {
        const int gstride = LB * 512;
        for (int e = ebase + blockIdx.x * 512 + tid; e < eend; e += gstride) {
            int row = __ldg(Lrow + e);
            int pos = __ldg(&g_rsL[row]) + __ldcg(&g_rankL[e]);
            g_eL[pos] = make_int2(__ldg(Lcol + e),
                                  __float_as_int(__ldg(Lval + e)));
        }
    }
}

// ---------------------------------------------------------------------------
// Power (best-known body): 1 thread/row, smem edge cache, __ldcg gathers,
// MLP8, lazy norm (1 barrier/iter), tree barrier with norm fold.
__global__ __launch_bounds__(PWT, 2)
void power_kernel(float* __restrict__ out) {
    extern __shared__ int2 sE[];
    __shared__ unsigned sense;
    __shared__ float wsum[PWT / 32];
    const int tid = threadIdx.x;
    const int lane = tid & 31, wid = tid >> 5;
    if (tid == 0) sense = g_sense;

    const int r0 = blockIdx.x * RPB;
    const int r1 = (r0 + RPB < NN) ? r0 + RPB : NN;
    const int s0 = __ldg(&g_rsL[r0]);
    const int e0 = __ldg(&g_rsL[r1]);
    const int cnt = min(e0 - s0, ECAP);
    for (int i = tid; i < cnt; i += PWT) sE[i] = __ldg(&g_eL[s0 + i]);

    const int r = r0 + tid;
    const bool active = (tid < RPB) && (r < NN);
    int s = 0, e = 0;
    if (active) {
        s = __ldg(&g_rsL[r]) - s0;
        e = __ldg(&g_rsL[r + 1]) - s0;
    }
    __syncthreads();

    float y = 0.f;
    for (int it = 0; it < ITERS; it++) {
        float alpha = 1.f;
        if (it > 0)
            alpha = 1.f / fmaxf(sqrtf(__ldcg(&g_norms[it - 1])), 1e-12f);
        const float* src = (it & 1) ? g_yb : g_ya;
        float* dst = (it & 1) ? g_ya : g_yb;

        float acc = 0.f;
        if (active) {
            int i = s;
            int elim = (e < ECAP) ? e : ECAP;
            for (; i + 7 < elim; i += 8) {
                int2 p0 = sE[i],     p1 = sE[i + 1], p2 = sE[i + 2], p3 = sE[i + 3];
                int2 p4 = sE[i + 4], p5 = sE[i + 5], p6 = sE[i + 6], p7 = sE[i + 7];
                float v0 = __ldcg(&src[p0.x]);
                float v1 = __ldcg(&src[p1.x]);
                float v2 = __ldcg(&src[p2.x]);
                float v3 = __ldcg(&src[p3.x]);
                float v4 = __ldcg(&src[p4.x]);
                float v5 = __ldcg(&src[p5.x]);
                float v6 = __ldcg(&src[p6.x]);
                float v7 = __ldcg(&src[p7.x]);
                acc += __int_as_float(p0.y) * v0 + __int_as_float(p1.y) * v1;
                acc += __int_as_float(p2.y) * v2 + __int_as_float(p3.y) * v3;
                acc += __int_as_float(p4.y) * v4 + __int_as_float(p5.y) * v5;
                acc += __int_as_float(p6.y) * v6 + __int_as_float(p7.y) * v7;
            }
            for (; i < elim; i++) {
                int2 p = sE[i];
                acc += __int_as_float(p.y) * __ldcg(&src[p.x]);
            }
            for (; i < e; i++) {
                int2 p = __ldg(&g_eL[s0 + i]);
                acc += __int_as_float(p.y) * __ldcg(&src[p.x]);
            }
        }

        float sq = 0.f;
        if (active) {
            float z = alpha * acc;
            float sg = (z > 0.f) ? 1.f : ((z < 0.f) ? -1.f : 0.f);
            y = z - TAU * sg;
            sq = y * y;
            __stcg(&dst[r], y);
        }
#pragma unroll
        for (int off = 16; off > 0; off >>= 1)
            sq += __shfl_down_sync(0xFFFFFFFFu, sq, off);
        if (lane == 0) wsum[wid] = sq;
        __syncthreads();
        if (wid == 0) {
            sq = (lane < (PWT >> 5)) ? wsum[lane] : 0.f;
#pragma unroll
            for (int off = 16; off > 0; off >>= 1)
                sq += __shfl_down_sync(0xFFFFFFFFu, sq, off);
            if (lane == 0)
                atomicAdd(&g_nleaf[(it * LEAFN + (blockIdx.x & (LEAFN - 1))) * 32], sq);
        }
        grid_sync_tree(&sense, blockIdx.x, CB, it);
    }

    if (active) {
        float inv = 1.f / fmaxf(sqrtf(__ldcg(&g_norms[ITERS - 1])), 1e-12f);
        out[r] = y * inv;
    }
}

// ---------------------------------------------------------------------------
extern "C" void kernel_launch(void* const* d_in, const int* in_sizes, int n_in,
                              void* d_out, int out_size) {
    const int*   A_row = (const int*)d_in[0];
    const int*   A_col = (const int*)d_in[1];
    const float* A_val = (const float*)d_in[2];
    const int*   L_row = (const int*)d_in[3];
    const int*   L_col = (const int*)d_in[4];
    const float* L_val = (const float*)d_in[5];
    const float* embed = (const float*)d_in[6];
    const float* W1    = (const float*)d_in[7];
    const float* W2    = (const float*)d_in[8];
    const float* Ws    = (const float*)d_in[9];
    const int E = in_sizes[0];
    float* out = (float*)d_out;

    float *X, *ya;
    cudaGetSymbolAddress((void**)&X,  g_X);
    cudaGetSymbolAddress((void**)&ya, g_ya);

    static int smem_set = 0;
    if (!smem_set) {
        cudaFuncSetAttribute(power_kernel,
                             cudaFuncAttributeMaxDynamicSharedMemorySize,
                             ECAP * (int)sizeof(int2));
        smem_set = 1;
    }

    // 1) CSR: ranks A+L, scans A+L, atomic-free scatter A
    csr_build_kernel<<<CB, CSRT>>>(A_row, A_col, A_val, L_row, E);

    // 2-3) layers; each also scatters half the L edges (atomic-free).
    //      layer2 writes scores only (no feature store).
    const int Ehalf = E / 2;
    layer_kernel<<<LB, 512>>>(embed, X, W1, Ws, ya, 0,
                              L_row, L_col, L_val, 0, Ehalf);
    layer_kernel<<<LB, 512>>>(X,     X, W2, Ws, ya, 1,
                              L_row, L_col, L_val, Ehalf, E);

    // 4) power iterations
    power_kernel<<<CB, PWT, ECAP * sizeof(int2)>>>(out);
}